// round 1
// baseline (speedup 1.0000x reference)
#include <cuda_runtime.h>
#include <cuda_bf16.h>
#include <math.h>

// Problem constants
#define NTOK   131072      // 32*4096 tokens
#define DIM    256
#define NCODE  1024
#define ND     (NTOK*DIM)  // 33554432

// GEMM tiling
#define KB     16          // k-chunk (dims per stage)
#define LDA    130         // padded A row (conflict-free transpose stores)
#define AS_FLOATS (2*KB*LDA)               // double-buffered A
#define BS_OFF    (AS_FLOATS*4)            // byte offset of B region
#define SMEM_BYTES (BS_OFF + 2*KB*128*8)   // + double-buffered float2 B = 49408

// ---- persistent device scratch (no allocations allowed) ----
__device__ float        g_cn[NCODE*DIM];   // normalized codebook
__device__ int          g_idx[NTOK];
__device__ unsigned int g_counts[NCODE];
__device__ double       g_sumsq;

// ============================================================
// init: zero per-launch accumulators
// ============================================================
__global__ void k_init() {
    int t = threadIdx.x;
    if (t < NCODE) g_counts[t] = 0u;
    if (t == 0)    g_sumsq = 0.0;
}

// ============================================================
// normalize codebook rows: cn = w / max(||w||, 1e-12)
// ============================================================
__global__ void k_norm(const float* __restrict__ w) {
    int row = blockIdx.x;
    int t   = threadIdx.x;                       // 64 threads
    float4 v = ((const float4*)(w + row*DIM))[t];
    float s  = v.x*v.x + v.y*v.y + v.z*v.z + v.w*v.w;
    #pragma unroll
    for (int o = 16; o > 0; o >>= 1) s += __shfl_xor_sync(0xffffffffu, s, o);
    __shared__ float ss[2];
    if ((t & 31) == 0) ss[t >> 5] = s;
    __syncthreads();
    float n = sqrtf(ss[0] + ss[1]);
    float r = 1.0f / fmaxf(n, 1e-12f);
    float4 o4 = make_float4(v.x*r, v.y*r, v.z*r, v.w*r);
    ((float4*)(g_cn + row*DIM))[t] = o4;
}

// ============================================================
// main: tiled dot-product + streaming argmax over 1024 codes
// block: 256 threads, 128 tokens; thread: 8 tokens x 8 codes via f32x2
// ============================================================
__global__ void __launch_bounds__(256, 2)
k_argmax(const float* __restrict__ z, float* __restrict__ out_idx_f) {
    extern __shared__ char sm[];
    float*  As = (float*) sm;                    // [2][KB][LDA]
    float2* Bs = (float2*)(sm + BS_OFF);         // [2][KB][128], duplicated {b,b}

    const int tid   = threadIdx.x;
    const int tx    = tid & 15;                  // token group 0..15
    const int ty    = tid >> 4;                  // code group  0..15
    const int mBase = blockIdx.x * 128;

    // loader mapping: f in [0,512) covered by tid and tid+256
    const int tokA = tid >> 2;                   // 0..63 (second half: +64)
    const int d4   = tid & 3;                    // which float4 of the 16-dim chunk

    unsigned long long acc[4][8];
    float best[8];
    int   bidx[8];
    #pragma unroll
    for (int i = 0; i < 8; i++) { best[i] = -3.4e38f; bidx[i] = 0; }
    #pragma unroll
    for (int p = 0; p < 4; p++)
        #pragma unroll
        for (int n = 0; n < 8; n++) acc[p][n] = 0ull;

    float4 pa0, pa1, pb0, pb1;

    // ---- prefetch stage 0 (nc=0, ks=0) ----
    {
        const float* za = z + (size_t)(mBase + tokA) * DIM;
        pa0 = *((const float4*)za + d4);
        pa1 = *((const float4*)(za + 64*DIM) + d4);
        const float* cb = g_cn + (size_t)tokA * DIM;
        pb0 = *((const float4*)cb + d4);
        pb1 = *((const float4*)(cb + 64*DIM) + d4);
    }
    // store stage 0 into buffer 0
    {
        float*  A = As;
        float2* B = Bs;
        int kr = d4 * 4;
        A[(kr+0)*LDA + tokA]      = pa0.x; A[(kr+1)*LDA + tokA]      = pa0.y;
        A[(kr+2)*LDA + tokA]      = pa0.z; A[(kr+3)*LDA + tokA]      = pa0.w;
        A[(kr+0)*LDA + tokA + 64] = pa1.x; A[(kr+1)*LDA + tokA + 64] = pa1.y;
        A[(kr+2)*LDA + tokA + 64] = pa1.z; A[(kr+3)*LDA + tokA + 64] = pa1.w;
        B[(kr+0)*128 + tokA]      = make_float2(pb0.x, pb0.x);
        B[(kr+1)*128 + tokA]      = make_float2(pb0.y, pb0.y);
        B[(kr+2)*128 + tokA]      = make_float2(pb0.z, pb0.z);
        B[(kr+3)*128 + tokA]      = make_float2(pb0.w, pb0.w);
        B[(kr+0)*128 + tokA + 64] = make_float2(pb1.x, pb1.x);
        B[(kr+1)*128 + tokA + 64] = make_float2(pb1.y, pb1.y);
        B[(kr+2)*128 + tokA + 64] = make_float2(pb1.z, pb1.z);
        B[(kr+3)*128 + tokA + 64] = make_float2(pb1.w, pb1.w);
    }
    __syncthreads();

    // ---- main loop: 8 code-chunks x 16 k-stages = 128 stages ----
    #pragma unroll 1
    for (int t = 0; t < 128; t++) {
        const int buf = t & 1;
        const bool has_next = (t + 1) < 128;

        // prefetch next stage's global loads
        if (has_next) {
            int tn  = t + 1;
            int ncn = tn >> 4;
            int k0  = (tn & 15) * KB;
            const float* za = z + (size_t)(mBase + tokA) * DIM + k0;
            pa0 = *((const float4*)za + d4);
            pa1 = *((const float4*)(za + 64*DIM) + d4);
            const float* cb = g_cn + (size_t)(ncn*128 + tokA) * DIM + k0;
            pb0 = *((const float4*)cb + d4);
            pb1 = *((const float4*)(cb + 64*DIM) + d4);
        }

        // compute current stage: 16 k-steps, 8x8 micro-tile in f32x2
        {
            const float*  A = As + buf * (KB*LDA);
            const float2* B = Bs + buf * (KB*128);
            #pragma unroll
            for (int kk = 0; kk < KB; kk++) {
                const float* ar = A + kk * LDA;
                unsigned long long a2[4];
                a2[0] = *(const unsigned long long*)(ar + tx*4);
                a2[1] = *(const unsigned long long*)(ar + tx*4 + 2);
                a2[2] = *(const unsigned long long*)(ar + 64 + tx*4);
                a2[3] = *(const unsigned long long*)(ar + 64 + tx*4 + 2);
                const float2* br = B + kk*128 + ty*8;
                unsigned long long b2[8];
                #pragma unroll
                for (int n = 0; n < 8; n++)
                    b2[n] = *(const unsigned long long*)(br + n);
                #pragma unroll
                for (int p = 0; p < 4; p++)
                    #pragma unroll
                    for (int n = 0; n < 8; n++)
                        asm("fma.rn.f32x2 %0, %1, %2, %0;"
                            : "+l"(acc[p][n]) : "l"(a2[p]), "l"(b2[n]));
            }
        }

        // end of a 128-code chunk: fold into running argmax, reset acc
        if ((t & 15) == 15) {
            int nc = t >> 4;
            int cBase = nc*128 + ty*8;
            #pragma unroll
            for (int p = 0; p < 4; p++) {
                #pragma unroll
                for (int n = 0; n < 8; n++) {
                    float lo = __uint_as_float((unsigned)(acc[p][n] & 0xffffffffull));
                    float hi = __uint_as_float((unsigned)(acc[p][n] >> 32));
                    int code = cBase + n;
                    if (lo > best[2*p])     { best[2*p]   = lo; bidx[2*p]   = code; }
                    if (hi > best[2*p + 1]) { best[2*p+1] = hi; bidx[2*p+1] = code; }
                    acc[p][n] = 0ull;
                }
            }
        }

        // store prefetched stage into the other buffer
        if (has_next) {
            float*  A = As + (buf ^ 1) * (KB*LDA);
            float2* B = Bs + (buf ^ 1) * (KB*128);
            int kr = d4 * 4;
            A[(kr+0)*LDA + tokA]      = pa0.x; A[(kr+1)*LDA + tokA]      = pa0.y;
            A[(kr+2)*LDA + tokA]      = pa0.z; A[(kr+3)*LDA + tokA]      = pa0.w;
            A[(kr+0)*LDA + tokA + 64] = pa1.x; A[(kr+1)*LDA + tokA + 64] = pa1.y;
            A[(kr+2)*LDA + tokA + 64] = pa1.z; A[(kr+3)*LDA + tokA + 64] = pa1.w;
            B[(kr+0)*128 + tokA]      = make_float2(pb0.x, pb0.x);
            B[(kr+1)*128 + tokA]      = make_float2(pb0.y, pb0.y);
            B[(kr+2)*128 + tokA]      = make_float2(pb0.z, pb0.z);
            B[(kr+3)*128 + tokA]      = make_float2(pb0.w, pb0.w);
            B[(kr+0)*128 + tokA + 64] = make_float2(pb1.x, pb1.x);
            B[(kr+1)*128 + tokA + 64] = make_float2(pb1.y, pb1.y);
            B[(kr+2)*128 + tokA + 64] = make_float2(pb1.z, pb1.z);
            B[(kr+3)*128 + tokA + 64] = make_float2(pb1.w, pb1.w);
        }
        __syncthreads();
    }

    // ---- cross-thread (ty) reduction: 16 candidates per token ----
    __syncthreads();
    float2* red = (float2*)sm;                   // [128 tokens][16] (reuses As)
    #pragma unroll
    for (int s = 0; s < 8; s++) {
        int p = s >> 1;
        int m = (p < 2 ? tx*4 + 2*p : 64 + tx*4 + 2*(p-2)) + (s & 1);
        red[m*16 + ty] = make_float2(best[s], __int_as_float(bidx[s]));
    }
    __syncthreads();
    if (tid < 128) {
        int m = tid;
        float bv = -3.4e38f;
        int   bi = 0x7fffffff;
        #pragma unroll
        for (int j = 0; j < 16; j++) {
            float2 e = red[m*16 + j];
            int ei = __float_as_int(e.y);
            if (e.x > bv || (e.x == bv && ei < bi)) { bv = e.x; bi = ei; }
        }
        int token = mBase + m;
        g_idx[token]     = bi;
        out_idx_f[token] = (float)bi;
        atomicAdd(&g_counts[bi], 1u);
    }
}

// ============================================================
// gather z_q = embed[idx], write out, accumulate sum((z_q - z)^2)
// one warp per token
// ============================================================
__global__ void k_gather(const float* __restrict__ z, const float* __restrict__ w,
                         float* __restrict__ out) {
    int wp    = threadIdx.x >> 5;
    int lane  = threadIdx.x & 31;
    int token = blockIdx.x * 8 + wp;
    int idx   = g_idx[token];
    const float4* e  = (const float4*)(w + (size_t)idx   * DIM);
    const float4* zz = (const float4*)(z + (size_t)token * DIM);
    float4*       o  = (float4*)(out + (size_t)token * DIM);
    float s = 0.f;
    #pragma unroll
    for (int r = 0; r < 2; r++) {
        int j = lane + r*32;
        float4 ev = e[j];
        float4 zv = zz[j];
        o[j] = ev;
        float dx = ev.x - zv.x, dy = ev.y - zv.y;
        float dz = ev.z - zv.z, dw = ev.w - zv.w;
        s += dx*dx + dy*dy + dz*dz + dw*dw;
    }
    #pragma unroll
    for (int off = 16; off > 0; off >>= 1) s += __shfl_xor_sync(0xffffffffu, s, off);
    __shared__ float ps[8];
    if (lane == 0) ps[wp] = s;
    __syncthreads();
    if (threadIdx.x == 0) {
        float tot = 0.f;
        #pragma unroll
        for (int i = 0; i < 8; i++) tot += ps[i];
        atomicAdd(&g_sumsq, (double)tot);
    }
}

// ============================================================
// finalize: loss + perplexity scalars
// ============================================================
__global__ void k_final(float* __restrict__ out) {
    int t = threadIdx.x;                         // 1024 threads
    float p    = (float)g_counts[t] / (float)NTOK;
    float term = p * logf(p + 1e-10f);
    #pragma unroll
    for (int off = 16; off > 0; off >>= 1) term += __shfl_xor_sync(0xffffffffu, term, off);
    __shared__ float ws[32];
    if ((t & 31) == 0) ws[t >> 5] = term;
    __syncthreads();
    if (t < 32) {
        float v = ws[t];
        #pragma unroll
        for (int off = 16; off > 0; off >>= 1) v += __shfl_xor_sync(0xffffffffu, v, off);
        if (t == 0) {
            out[ND]     = (float)(1.25 * (g_sumsq / (double)ND));  // (1+BETA)*mean
            out[ND + 1] = expf(-v);                                // perplexity
        }
    }
}

// ============================================================
extern "C" void kernel_launch(void* const* d_in, const int* in_sizes, int n_in,
                              void* d_out, int out_size) {
    const float* z = (const float*)d_in[0];      // [131072, 256]
    const float* w = (const float*)d_in[1];      // [1024, 256]
    float* out = (float*)d_out;                  // zq | loss | perp | indices

    cudaFuncSetAttribute(k_argmax, cudaFuncAttributeMaxDynamicSharedMemorySize, SMEM_BYTES);

    k_init  <<<1, 1024>>>();
    k_norm  <<<NCODE, 64>>>(w);
    k_argmax<<<NTOK/128, 256, SMEM_BYTES>>>(z, out + ND + 2);
    k_gather<<<NTOK/8, 256>>>(z, w, out);
    k_final <<<1, 1024>>>(out);
}

// round 6
// speedup vs baseline: 2.2136x; 2.2136x over previous
#include <cuda_runtime.h>
#include <cuda_bf16.h>
#include <math.h>
#include <stdint.h>

#define NTOK   131072
#define DIM    256
#define NCODE  1024
#define ND     (NTOK*DIM)

// smem: A = 128 tok x 512 vk x bf16 = 128KB ; B = 2 x (128 codes x 64 vk) = 32KB
#define SMEM_A_BYTES   131072
#define SMEM_B_STAGE   16384
#define SMEM_TOTAL     (SMEM_A_BYTES + 2*SMEM_B_STAGE)

// ---------------- persistent device scratch ----------------
__device__ float          g_cn[NCODE*DIM];      // normalized codebook fp32
__device__ __nv_bfloat16  g_cb_hi[NCODE*DIM];   // bf16 hi split of cn
__device__ __nv_bfloat16  g_cb_lo[NCODE*DIM];   // bf16 lo split of cn
__device__ int            g_c1[NTOK];
__device__ int            g_c2[NTOK];
__device__ unsigned int   g_counts[NCODE];
__device__ double         g_sumsq;

__device__ __forceinline__ uint32_t smem_u32(const void* p) {
    uint32_t a;
    asm("{ .reg .u64 t; cvta.to.shared.u64 t, %1; cvt.u32.u64 %0, t; }" : "=r"(a) : "l"(p));
    return a;
}

#define LDSM4(r0,r1,r2,r3,a) \
    asm volatile("ldmatrix.sync.aligned.m8n8.x4.shared.b16 {%0,%1,%2,%3}, [%4];" \
        : "=r"(r0),"=r"(r1),"=r"(r2),"=r"(r3) : "r"(a))

#define MMA16816(d,a0,a1,a2,a3,b0,b1) \
    asm volatile("mma.sync.aligned.m16n8k16.row.col.f32.bf16.bf16.f32 " \
        "{%0,%1,%2,%3},{%4,%5,%6,%7},{%8,%9},{%0,%1,%2,%3};" \
        : "+f"((d)[0]),"+f"((d)[1]),"+f"((d)[2]),"+f"((d)[3]) \
        : "r"(a0),"r"(a1),"r"(a2),"r"(a3),"r"(b0),"r"(b1))

// ============================================================
__global__ void k_init() {
    int t = threadIdx.x;
    if (t < NCODE) g_counts[t] = 0u;
    if (t == 0)    g_sumsq = 0.0;
}

// ============================================================
// normalize codebook + bf16 hi/lo splits
// ============================================================
__global__ void k_norm(const float* __restrict__ w) {
    int row = blockIdx.x;
    int t   = threadIdx.x;                       // 64 threads
    float4 v = ((const float4*)(w + row*DIM))[t];
    float s  = v.x*v.x + v.y*v.y + v.z*v.z + v.w*v.w;
    #pragma unroll
    for (int o = 16; o > 0; o >>= 1) s += __shfl_xor_sync(0xffffffffu, s, o);
    __shared__ float ss[2];
    if ((t & 31) == 0) ss[t >> 5] = s;
    __syncthreads();
    float n = sqrtf(ss[0] + ss[1]);
    float r = 1.0f / fmaxf(n, 1e-12f);
    float c[4] = { v.x*r, v.y*r, v.z*r, v.w*r };
    ((float4*)(g_cn + row*DIM))[t] = make_float4(c[0], c[1], c[2], c[3]);
    union { __nv_bfloat16 h[4]; uint2 u; } hi, lo;
    #pragma unroll
    for (int i = 0; i < 4; i++) {
        hi.h[i] = __float2bfloat16(c[i]);
        lo.h[i] = __float2bfloat16(c[i] - __bfloat162float(hi.h[i]));
    }
    ((uint2*)(g_cb_hi + row*DIM))[t] = hi.u;
    ((uint2*)(g_cb_lo + row*DIM))[t] = lo.u;
}

// ============================================================
// HMMA GEMM + streaming top-2 argmax
// CTA: 128 tokens, 256 thr, 8 warps (4 m-groups x 2 n-groups).
// Virtual K passes per N-tile: (A_hi,B_hi),(A_hi,B_lo),(A_lo,B_hi),
// each K=256 streamed as 4 chunks of 64 -> 12 stages/tile, 96 total.
// Final: cross-wn top-2 merge through smem (both n-halves).
// ============================================================
__global__ void __launch_bounds__(256, 1)
k_gemm(const float* __restrict__ z) {
    extern __shared__ char sm[];
    char* As = sm;
    char* Bs = sm + SMEM_A_BYTES;
    const uint32_t sb = smem_u32(sm);

    const int tid  = threadIdx.x;
    const int wid  = tid >> 5, lane = tid & 31;
    const int wm   = wid & 3,  wn   = wid >> 2;
    const int mBase = blockIdx.x * 128;

    // ---- A fill: z fp32 -> bf16 hi|lo, swizzled ----
    {
        const float4* zsrc = (const float4*)(z + (size_t)mBase * DIM);
        #pragma unroll 4
        for (int i = 0; i < 32; i++) {
            int idx = i*256 + tid;              // float4 index, 8192 total
            int tok = idx >> 6, d4 = idx & 63;
            float4 v = zsrc[idx];
            float vv[4] = { v.x, v.y, v.z, v.w };
            union { __nv_bfloat16 h[4]; uint2 u; } hi, lo;
            #pragma unroll
            for (int q = 0; q < 4; q++) {
                hi.h[q] = __float2bfloat16(vv[q]);
                lo.h[q] = __float2bfloat16(vv[q] - __bfloat162float(hi.h[q]));
            }
            int xo = (tok & 7) * 16;
            *(uint2*)(As + tok*1024 +       ((d4*8) ^ xo)) = hi.u;
            *(uint2*)(As + tok*1024 + 512 + ((d4*8) ^ xo)) = lo.u;
        }
    }
    // ---- B stage 0 (nt=0, pass hi, chunk 0) ----
    {
        const uint4* src = (const uint4*)g_cb_hi;
        #pragma unroll
        for (int i = 0; i < 4; i++) {
            int j = i*256 + tid;                // uint4 index, 1024 total
            int code = j >> 3, ku = j & 7;
            uint4 v = src[code*32 + ku];
            *(uint4*)(Bs + code*128 + ((ku*16) ^ ((code & 7)*16))) = v;
        }
    }
    __syncthreads();

    // ---- per-lane ldmatrix address components ----
    const int lr  = lane & 7;
    const int l8  = (lane >> 3) & 1;
    const int l16 = (lane >> 4) & 1;
    const uint32_t aBase = sb + (uint32_t)(wm*32 + lr + l8*8) * 1024;
    const uint32_t kaddA = (uint32_t)(l16 * 16);
    const uint32_t bBase = sb + SMEM_A_BYTES + (uint32_t)(wn*64 + l16*8 + lr) * 128;
    const uint32_t kaddB = (uint32_t)(l8 * 16);
    const uint32_t lXor  = (uint32_t)(lr * 16);

    float acc[64];                               // [mt][t8][reg] = mt*32+t8*4+r
    #pragma unroll
    for (int i = 0; i < 64; i++) acc[i] = 0.f;

    float v1[4], v2[4]; int i1[4], i2[4];        // top2 per (mt, rowgroup)
    #pragma unroll
    for (int s = 0; s < 4; s++) { v1[s] = v2[s] = -3.4e38f; i1[s] = i2[s] = 0; }

    uint4 stg[4];

    #pragma unroll 1
    for (int g = 0; g < 96; g++) {
        const int nt = g / 12, ss = g % 12, p = ss >> 2, c = ss & 3;

        // prefetch next stage's B into regs
        if (g < 95) {
            int g2 = g + 1, nt2 = g2 / 12, ss2 = g2 % 12;
            int p2 = ss2 >> 2, c2 = ss2 & 3;
            const uint4* src = (const uint4*)((p2 == 1) ? g_cb_lo : g_cb_hi);
            #pragma unroll
            for (int i = 0; i < 4; i++) {
                int j = i*256 + tid;
                int code = j >> 3, ku = j & 7;
                stg[i] = src[(size_t)(nt2*128 + code)*32 + c2*8 + ku];
            }
        }

        // ---- compute this stage: 4 k16-steps ----
        {
            const uint32_t Aoffp = (p == 2) ? 512u : 0u;
            const uint32_t bufB  = (uint32_t)(g & 1) * SMEM_B_STAGE;
            #pragma unroll
            for (int kk = 0; kk < 4; kk++) {
                uint32_t kbA = Aoffp + (uint32_t)(c*128 + kk*32);
                uint32_t aAddr = aBase + ((kbA + kaddA) ^ lXor);
                uint32_t a0[4], a1[4];
                LDSM4(a0[0], a0[1], a0[2], a0[3], aAddr);
                LDSM4(a1[0], a1[1], a1[2], a1[3], aAddr + 16384);

                uint32_t kbB = (uint32_t)(kk*32) + kaddB;
                uint32_t bAddr = bBase + bufB + (kbB ^ lXor);
                uint32_t bf[16];
                #pragma unroll
                for (int gb = 0; gb < 4; gb++)
                    LDSM4(bf[gb*4+0], bf[gb*4+1], bf[gb*4+2], bf[gb*4+3],
                          bAddr + (uint32_t)gb*2048);
                // bf[gb*4+0..1] = n8 tile (2*gb) frags b0,b1 ; +2..3 = tile 2*gb+1

                #pragma unroll
                for (int t8 = 0; t8 < 8; t8++) {
                    uint32_t b0 = bf[(t8 >> 1)*4 + (t8 & 1)*2 + 0];
                    uint32_t b1 = bf[(t8 >> 1)*4 + (t8 & 1)*2 + 1];
                    MMA16816(&acc[t8*4],      a0[0], a0[1], a0[2], a0[3], b0, b1);
                    MMA16816(&acc[32 + t8*4], a1[0], a1[1], a1[2], a1[3], b0, b1);
                }
            }
        }

        // ---- N-tile done: fold into top-2, reset acc ----
        if (ss == 11) {
            int cBase = nt*128 + wn*64 + (lane & 3)*2;
            #pragma unroll
            for (int mt = 0; mt < 2; mt++) {
                #pragma unroll
                for (int rg = 0; rg < 2; rg++) {
                    int s = mt*2 + rg;
                    #pragma unroll
                    for (int t8 = 0; t8 < 8; t8++) {
                        #pragma unroll
                        for (int e = 0; e < 2; e++) {
                            float v = acc[mt*32 + t8*4 + rg*2 + e];
                            int code = cBase + t8*8 + e;
                            if (v > v1[s])      { v2[s] = v1[s]; i2[s] = i1[s]; v1[s] = v; i1[s] = code; }
                            else if (v > v2[s]) { v2[s] = v;     i2[s] = code; }
                        }
                    }
                }
            }
            #pragma unroll
            for (int i = 0; i < 64; i++) acc[i] = 0.f;
        }

        // ---- store prefetched B into other buffer ----
        if (g < 95) {
            char* dst = Bs + ((g + 1) & 1) * SMEM_B_STAGE;
            #pragma unroll
            for (int i = 0; i < 4; i++) {
                int j = i*256 + tid;
                int code = j >> 3, ku = j & 7;
                *(uint4*)(dst + code*128 + ((ku*16) ^ ((code & 7)*16))) = stg[i];
            }
        }
        __syncthreads();
    }

    // ---- cross-lane top-2 merge (lanes sharing lane>>2, code cols) ----
    #pragma unroll
    for (int mask = 1; mask <= 2; mask <<= 1) {
        #pragma unroll
        for (int s = 0; s < 4; s++) {
            float w1 = __shfl_xor_sync(0xffffffffu, v1[s], mask);
            int   j1 = __shfl_xor_sync(0xffffffffu, i1[s], mask);
            float w2 = __shfl_xor_sync(0xffffffffu, v2[s], mask);
            int   j2 = __shfl_xor_sync(0xffffffffu, i2[s], mask);
            if (w1 > v1[s]) {
                if (v1[s] >= w2) { v2[s] = v1[s]; i2[s] = i1[s]; }
                else             { v2[s] = w2;    i2[s] = j2;    }
                v1[s] = w1; i1[s] = j1;
            } else if (w1 > v2[s]) {
                v2[s] = w1; i2[s] = j1;
            }
        }
    }

    // ---- cross-warp (wn) top-2 merge through smem (As is dead now) ----
    float4* red = (float4*)sm;                   // [128 tokens][2 wn]
    if ((lane & 3) == 0) {
        int row = lane >> 2;
        #pragma unroll
        for (int mt = 0; mt < 2; mt++)
            #pragma unroll
            for (int rg = 0; rg < 2; rg++) {
                int s  = mt*2 + rg;
                int tl = wm*32 + mt*16 + rg*8 + row;
                red[tl*2 + wn] = make_float4(v1[s], __int_as_float(i1[s]),
                                             v2[s], __int_as_float(i2[s]));
            }
    }
    __syncthreads();
    if (tid < 128) {
        float4 a = red[tid*2], b = red[tid*2 + 1];   // each sorted desc
        float bv1, bv2; int c1i, c2i;
        int ai1 = __float_as_int(a.y), bi1 = __float_as_int(b.y);
        if (a.x > b.x || (a.x == b.x && ai1 < bi1)) {
            bv1 = a.x; c1i = ai1;
            if (a.z >= b.x) { bv2 = a.z; c2i = __float_as_int(a.w); }
            else            { bv2 = b.x; c2i = bi1; }
        } else {
            bv1 = b.x; c1i = bi1;
            if (b.z >= a.x) { bv2 = b.z; c2i = __float_as_int(b.w); }
            else            { bv2 = a.x; c2i = ai1; }
        }
        (void)bv1; (void)bv2;
        int token = mBase + tid;
        g_c1[token] = c1i;
        g_c2[token] = c2i;
    }
}

// ============================================================
// fp32 rescore top-2 + gather z_q + loss accum + counts
// ============================================================
__global__ void k_fin(const float* __restrict__ z, const float* __restrict__ w,
                      float* __restrict__ out) {
    int wp = threadIdx.x >> 5, lane = threadIdx.x & 31;
    int token = blockIdx.x*8 + wp;
    int c1 = g_c1[token], c2 = g_c2[token];
    const float4* zz = (const float4*)(z    + (size_t)token*DIM);
    const float4* p1 = (const float4*)(g_cn + (size_t)c1*DIM);
    const float4* p2 = (const float4*)(g_cn + (size_t)c2*DIM);
    float4 zv[2];
    float d1 = 0.f, d2 = 0.f;
    #pragma unroll
    for (int rr = 0; rr < 2; rr++) {
        int j = lane + rr*32;
        zv[rr] = zz[j];
        float4 a = p1[j], b = p2[j];
        d1 += zv[rr].x*a.x + zv[rr].y*a.y + zv[rr].z*a.z + zv[rr].w*a.w;
        d2 += zv[rr].x*b.x + zv[rr].y*b.y + zv[rr].z*b.z + zv[rr].w*b.w;
    }
    #pragma unroll
    for (int o = 16; o > 0; o >>= 1) {
        d1 += __shfl_xor_sync(0xffffffffu, d1, o);
        d2 += __shfl_xor_sync(0xffffffffu, d2, o);
    }
    int win = (d1 > d2) ? c1 : ((d2 > d1) ? c2 : min(c1, c2));

    const float4* e  = (const float4*)(w + (size_t)win*DIM);
    float4*       o4 = (float4*)(out + (size_t)token*DIM);
    float s = 0.f;
    #pragma unroll
    for (int rr = 0; rr < 2; rr++) {
        int j = lane + rr*32;
        float4 ev = e[j];
        o4[j] = ev;
        float dx = ev.x - zv[rr].x, dy = ev.y - zv[rr].y;
        float dz = ev.z - zv[rr].z, dw = ev.w - zv[rr].w;
        s += dx*dx + dy*dy + dz*dz + dw*dw;
    }
    #pragma unroll
    for (int o = 16; o > 0; o >>= 1) s += __shfl_xor_sync(0xffffffffu, s, o);
    if (lane == 0) {
        out[ND + 2 + token] = (float)win;
        atomicAdd(&g_counts[win], 1u);
    }
    __shared__ float ps[8];
    if (lane == 0) ps[wp] = s;
    __syncthreads();
    if (threadIdx.x == 0) {
        float tot = 0.f;
        #pragma unroll
        for (int i = 0; i < 8; i++) tot += ps[i];
        atomicAdd(&g_sumsq, (double)tot);
    }
}

// ============================================================
__global__ void k_final(float* __restrict__ out) {
    int t = threadIdx.x;                         // 1024 threads
    float p    = (float)g_counts[t] / (float)NTOK;
    float term = p * logf(p + 1e-10f);
    #pragma unroll
    for (int o = 16; o > 0; o >>= 1) term += __shfl_xor_sync(0xffffffffu, term, o);
    __shared__ float ws[32];
    if ((t & 31) == 0) ws[t >> 5] = term;
    __syncthreads();
    if (t < 32) {
        float v = ws[t];
        #pragma unroll
        for (int o = 16; o > 0; o >>= 1) v += __shfl_xor_sync(0xffffffffu, v, o);
        if (t == 0) {
            out[ND]     = (float)(1.25 * (g_sumsq / (double)ND));
            out[ND + 1] = expf(-v);
        }
    }
}

// ============================================================
extern "C" void kernel_launch(void* const* d_in, const int* in_sizes, int n_in,
                              void* d_out, int out_size) {
    const float* z = (const float*)d_in[0];      // [131072, 256]
    const float* w = (const float*)d_in[1];      // [1024, 256]
    float* out = (float*)d_out;

    cudaFuncSetAttribute(k_gemm, cudaFuncAttributeMaxDynamicSharedMemorySize, SMEM_TOTAL);

    k_init <<<1, 1024>>>();
    k_norm <<<NCODE, 64>>>(w);
    k_gemm <<<NTOK/128, 256, SMEM_TOTAL>>>(z);
    k_fin  <<<NTOK/8, 256>>>(z, w, out);
    k_final<<<1, 1024>>>(out);
}

// round 7
// speedup vs baseline: 4.8585x; 2.1948x over previous
#include <cuda_runtime.h>
#include <cuda_bf16.h>
#include <math.h>
#include <stdint.h>

#define NTOK   131072
#define DIM    256
#define NCODE  1024
#define ND     (NTOK*DIM)

// smem: A = 128 tok x 256 k x bf16 = 64KB ; B = 3 x (128 codes x 64 k) = 48KB
#define SMEM_A_BYTES   65536
#define SMEM_B_STAGE   16384
#define SMEM_TOTAL     (SMEM_A_BYTES + 3*SMEM_B_STAGE)   // 114688

// ---------------- persistent device scratch ----------------
__device__ float          g_cn[NCODE*DIM];      // normalized codebook fp32
__device__ __nv_bfloat16  g_cb_hi[NCODE*DIM];   // bf16 codebook
__device__ int4           g_cand[NTOK];         // top-4 candidates per token
__device__ unsigned int   g_counts[NCODE];
__device__ double         g_sumsq;

__device__ __forceinline__ uint32_t smem_u32(const void* p) {
    uint32_t a;
    asm("{ .reg .u64 t; cvta.to.shared.u64 t, %1; cvt.u32.u64 %0, t; }" : "=r"(a) : "l"(p));
    return a;
}

#define LDSM4(r0,r1,r2,r3,a) \
    asm volatile("ldmatrix.sync.aligned.m8n8.x4.shared.b16 {%0,%1,%2,%3}, [%4];" \
        : "=r"(r0),"=r"(r1),"=r"(r2),"=r"(r3) : "r"(a))

#define MMA16816(d,a0,a1,a2,a3,b0,b1) \
    asm volatile("mma.sync.aligned.m16n8k16.row.col.f32.bf16.bf16.f32 " \
        "{%0,%1,%2,%3},{%4,%5,%6,%7},{%8,%9},{%0,%1,%2,%3};" \
        : "+f"((d)[0]),"+f"((d)[1]),"+f"((d)[2]),"+f"((d)[3]) \
        : "r"(a0),"r"(a1),"r"(a2),"r"(a3),"r"(b0),"r"(b1))

#define CP_ASYNC16(dst, src) \
    asm volatile("cp.async.cg.shared.global [%0], [%1], 16;" :: "r"(dst), "l"(src))
#define CP_COMMIT() asm volatile("cp.async.commit_group;" ::: "memory")
#define CP_WAIT1()  asm volatile("cp.async.wait_group 1;"  ::: "memory")
#define CP_WAIT0()  asm volatile("cp.async.wait_group 0;"  ::: "memory")

// ============================================================
__global__ void k_init() {
    int t = threadIdx.x;
    if (t < NCODE) g_counts[t] = 0u;
    if (t == 0)    g_sumsq = 0.0;
}

// ============================================================
// normalize codebook + bf16 conversion
// ============================================================
__global__ void k_norm(const float* __restrict__ w) {
    int row = blockIdx.x;
    int t   = threadIdx.x;                       // 64 threads
    float4 v = ((const float4*)(w + row*DIM))[t];
    float s  = v.x*v.x + v.y*v.y + v.z*v.z + v.w*v.w;
    #pragma unroll
    for (int o = 16; o > 0; o >>= 1) s += __shfl_xor_sync(0xffffffffu, s, o);
    __shared__ float ss[2];
    if ((t & 31) == 0) ss[t >> 5] = s;
    __syncthreads();
    float n = sqrtf(ss[0] + ss[1]);
    float r = 1.0f / fmaxf(n, 1e-12f);
    float c[4] = { v.x*r, v.y*r, v.z*r, v.w*r };
    ((float4*)(g_cn + row*DIM))[t] = make_float4(c[0], c[1], c[2], c[3]);
    union { __nv_bfloat16 h[4]; uint2 u; } hi;
    #pragma unroll
    for (int i = 0; i < 4; i++) hi.h[i] = __float2bfloat16(c[i]);
    ((uint2*)(g_cb_hi + row*DIM))[t] = hi.u;
}

// ============================================================
// 1-pass bf16 HMMA GEMM + streaming per-thread top-3 ->
// token top-4 candidates. CTA: 128 tokens, 8 warps (4m x 2n).
// K=256 in 4 chunks of 64 per N-tile, 8 N-tiles -> 32 stages.
// B: 3-stage cp.async pipeline. 2 CTAs/SM.
// ============================================================
__global__ void __launch_bounds__(256, 2)
k_gemm(const float* __restrict__ z) {
    extern __shared__ char sm[];
    char* As = sm;
    const uint32_t sb = smem_u32(sm);

    const int tid  = threadIdx.x;
    const int wid  = tid >> 5, lane = tid & 31;
    const int wm   = wid & 3,  wn   = wid >> 2;
    const int mBase = blockIdx.x * 128;

    // ---- A fill: z fp32 -> bf16, swizzled (512B rows) ----
    {
        const float4* zsrc = (const float4*)(z + (size_t)mBase * DIM);
        #pragma unroll 4
        for (int i = 0; i < 32; i++) {
            int idx = i*256 + tid;              // float4 index, 8192 total
            int tok = idx >> 6, d4 = idx & 63;
            float4 v = zsrc[idx];
            union { __nv_bfloat16 h[4]; uint2 u; } hi;
            hi.h[0] = __float2bfloat16(v.x);
            hi.h[1] = __float2bfloat16(v.y);
            hi.h[2] = __float2bfloat16(v.z);
            hi.h[3] = __float2bfloat16(v.w);
            *(uint2*)(As + tok*512 + ((d4*8) ^ ((tok & 7)*16))) = hi.u;
        }
    }

    // ---- cp.async B stage issue helper (inlined twice + loop) ----
    const int bcode0 = tid >> 3;                 // code for i=0 (others +32*i)
    const int bku    = tid & 7;
    // per-i dst offsets within a stage
    uint32_t bdst[4];
    #pragma unroll
    for (int i = 0; i < 4; i++) {
        int code = bcode0 + i*32;
        bdst[i] = (uint32_t)(code*128 + ((bku*16) ^ ((code & 7)*16)));
    }
    const char* bsrc0 = (const char*)g_cb_hi + (size_t)bcode0*512 + bku*16;

    // prologue: issue stages 0 and 1
    #pragma unroll
    for (int st = 0; st < 2; st++) {
        const char* src = bsrc0 + (size_t)st*16384;  // stage st: nt=st>>2(=0), c=st -> c*64 elems = 128B? no:
        // stage byte offset: nt*128 rows *512B + c*128B ; st<2 -> nt=0, c=st
        src = bsrc0 + (size_t)(st & 3)*128 + (size_t)(st >> 2)*65536;
        uint32_t dbase = sb + SMEM_A_BYTES + (uint32_t)st*SMEM_B_STAGE;
        #pragma unroll
        for (int i = 0; i < 4; i++)
            CP_ASYNC16(dbase + bdst[i], src + (size_t)i*16384);
        CP_COMMIT();
    }

    // ---- per-lane ldmatrix address components ----
    const int lr  = lane & 7;
    const int l8  = (lane >> 3) & 1;
    const int l16 = (lane >> 4) & 1;
    const uint32_t aBase = sb + (uint32_t)(wm*32 + lr + l8*8) * 512;
    const uint32_t kaddA = (uint32_t)(l16 * 16);
    const uint32_t bBase = sb + SMEM_A_BYTES + (uint32_t)(wn*64 + l16*8 + lr) * 128;
    const uint32_t kaddB = (uint32_t)(l8 * 16);
    const uint32_t lXor  = (uint32_t)(lr * 16);

    float acc[64];
    #pragma unroll
    for (int i = 0; i < 64; i++) acc[i] = 0.f;

    float v1[4], v2[4], v3[4]; int i1[4], i2[4], i3[4];
    #pragma unroll
    for (int s = 0; s < 4; s++) {
        v1[s] = v2[s] = v3[s] = -3.4e38f;
        i1[s] = i2[s] = i3[s] = 0;
    }

    int bufs[3] = { 0, 1, 2 };  (void)bufs;

    #pragma unroll 1
    for (int g = 0; g < 32; g++) {
        const int c = g & 3;

        if (g == 31) { CP_WAIT0(); } else { CP_WAIT1(); }
        __syncthreads();

        // ---- compute stage g: 4 k16-steps ----
        {
            const uint32_t bufB = (uint32_t)(g % 3) * SMEM_B_STAGE;
            #pragma unroll
            for (int kk = 0; kk < 4; kk++) {
                uint32_t kbA = (uint32_t)(c*128 + kk*32);
                uint32_t aAddr = aBase + ((kbA + kaddA) ^ lXor);
                uint32_t a0[4], a1[4];
                LDSM4(a0[0], a0[1], a0[2], a0[3], aAddr);
                LDSM4(a1[0], a1[1], a1[2], a1[3], aAddr + 8192);

                uint32_t kbB = (uint32_t)(kk*32) + kaddB;
                uint32_t bAddr = bBase + bufB + (kbB ^ lXor);
                #pragma unroll
                for (int gb = 0; gb < 2; gb++) {
                    uint32_t bf[8];
                    LDSM4(bf[0], bf[1], bf[2], bf[3], bAddr + (uint32_t)(2*gb)*2048);
                    LDSM4(bf[4], bf[5], bf[6], bf[7], bAddr + (uint32_t)(2*gb+1)*2048);
                    #pragma unroll
                    for (int tt = 0; tt < 4; tt++) {
                        int t8 = gb*4 + tt;
                        uint32_t b0 = bf[(tt >> 1)*4 + (tt & 1)*2 + 0];
                        uint32_t b1 = bf[(tt >> 1)*4 + (tt & 1)*2 + 1];
                        MMA16816(&acc[t8*4],      a0[0], a0[1], a0[2], a0[3], b0, b1);
                        MMA16816(&acc[32 + t8*4], a1[0], a1[1], a1[2], a1[3], b0, b1);
                    }
                }
            }
        }

        // ---- N-tile done: fold into per-thread top-3, reset acc ----
        if (c == 3) {
            int nt = g >> 2;
            int cBase = nt*128 + wn*64 + (lane & 3)*2;
            #pragma unroll
            for (int mt = 0; mt < 2; mt++) {
                #pragma unroll
                for (int rg = 0; rg < 2; rg++) {
                    int s = mt*2 + rg;
                    #pragma unroll
                    for (int t8 = 0; t8 < 8; t8++) {
                        #pragma unroll
                        for (int e = 0; e < 2; e++) {
                            float v = acc[mt*32 + t8*4 + rg*2 + e];
                            int code = cBase + t8*8 + e;
                            if (v > v1[s]) {
                                v3[s]=v2[s]; i3[s]=i2[s];
                                v2[s]=v1[s]; i2[s]=i1[s];
                                v1[s]=v;     i1[s]=code;
                            } else if (v > v2[s]) {
                                v3[s]=v2[s]; i3[s]=i2[s];
                                v2[s]=v;     i2[s]=code;
                            } else if (v > v3[s]) {
                                v3[s]=v;     i3[s]=code;
                            }
                        }
                    }
                }
            }
            #pragma unroll
            for (int i = 0; i < 64; i++) acc[i] = 0.f;
        }

        // ---- issue stage g+2 into buffer (g+2)%3 ----
        if (g + 2 < 32) {
            int st = g + 2;
            const char* src = bsrc0 + (size_t)(st & 3)*128 + (size_t)(st >> 2)*65536;
            uint32_t dbase = sb + SMEM_A_BYTES + (uint32_t)(st % 3)*SMEM_B_STAGE;
            #pragma unroll
            for (int i = 0; i < 4; i++)
                CP_ASYNC16(dbase + bdst[i], src + (size_t)i*16384);
            CP_COMMIT();
        }
    }

    // ---- dump per-thread top-3 to smem, merge to token top-4 ----
    __syncthreads();
    float2* red = (float2*)sm;                   // [128 tok][8 q][3]
    {
        int q = wn*4 + (lane & 3);
        int row = lane >> 2;
        #pragma unroll
        for (int mt = 0; mt < 2; mt++)
            #pragma unroll
            for (int rg = 0; rg < 2; rg++) {
                int s  = mt*2 + rg;
                int tl = wm*32 + mt*16 + rg*8 + row;
                float2* e = red + (tl*8 + q)*3;
                e[0] = make_float2(v1[s], __int_as_float(i1[s]));
                e[1] = make_float2(v2[s], __int_as_float(i2[s]));
                e[2] = make_float2(v3[s], __int_as_float(i3[s]));
            }
    }
    __syncthreads();
    if (tid < 128) {
        float t1=-3.4e38f, t2=-3.4e38f, t3=-3.4e38f, t4=-3.4e38f;
        int   c1=0, c2=0, c3=0, c4=0;
        const float2* e = red + tid*24;
        #pragma unroll 4
        for (int j = 0; j < 24; j++) {
            float v = e[j].x; int cd = __float_as_int(e[j].y);
            if (v > t1)      { t4=t3;c4=c3; t3=t2;c3=c2; t2=t1;c2=c1; t1=v;c1=cd; }
            else if (v > t2) { t4=t3;c4=c3; t3=t2;c3=c2; t2=v;c2=cd; }
            else if (v > t3) { t4=t3;c4=c3; t3=v;c3=cd; }
            else if (v > t4) { t4=v;c4=cd; }
        }
        g_cand[mBase + tid] = make_int4(c1, c2, c3, c4);
    }
}

// ============================================================
// fp32 rescore of 4 candidates + gather z_q + loss + counts
// one warp per token
// ============================================================
__global__ void k_fin(const float* __restrict__ z, const float* __restrict__ w,
                      float* __restrict__ out) {
    int wp = threadIdx.x >> 5, lane = threadIdx.x & 31;
    int token = blockIdx.x*8 + wp;
    int4 cd = g_cand[token];
    int cand[4] = { cd.x, cd.y, cd.z, cd.w };

    const float4* zz = (const float4*)(z + (size_t)token*DIM);
    const float4* pc[4];
    #pragma unroll
    for (int q = 0; q < 4; q++) pc[q] = (const float4*)(g_cn + (size_t)cand[q]*DIM);

    float4 zv[2];
    float d[4] = { 0.f, 0.f, 0.f, 0.f };
    #pragma unroll
    for (int rr = 0; rr < 2; rr++) {
        int j = lane + rr*32;
        zv[rr] = zz[j];
        #pragma unroll
        for (int q = 0; q < 4; q++) {
            float4 a = pc[q][j];
            d[q] += zv[rr].x*a.x + zv[rr].y*a.y + zv[rr].z*a.z + zv[rr].w*a.w;
        }
    }
    #pragma unroll
    for (int o = 16; o > 0; o >>= 1)
        #pragma unroll
        for (int q = 0; q < 4; q++)
            d[q] += __shfl_xor_sync(0xffffffffu, d[q], o);

    float bd = -3.4e38f; int win = 0x7fffffff;
    #pragma unroll
    for (int q = 0; q < 4; q++)
        if (d[q] > bd || (d[q] == bd && cand[q] < win)) { bd = d[q]; win = cand[q]; }

    const float4* e  = (const float4*)(w + (size_t)win*DIM);
    float4*       o4 = (float4*)(out + (size_t)token*DIM);
    float s = 0.f;
    #pragma unroll
    for (int rr = 0; rr < 2; rr++) {
        int j = lane + rr*32;
        float4 ev = e[j];
        o4[j] = ev;
        float dx = ev.x - zv[rr].x, dy = ev.y - zv[rr].y;
        float dz = ev.z - zv[rr].z, dw = ev.w - zv[rr].w;
        s += dx*dx + dy*dy + dz*dz + dw*dw;
    }
    #pragma unroll
    for (int o = 16; o > 0; o >>= 1) s += __shfl_xor_sync(0xffffffffu, s, o);
    if (lane == 0) {
        out[ND + 2 + token] = (float)win;
        atomicAdd(&g_counts[win], 1u);
    }
    __shared__ float ps[8];
    if (lane == 0) ps[wp] = s;
    __syncthreads();
    if (threadIdx.x == 0) {
        float tot = 0.f;
        #pragma unroll
        for (int i = 0; i < 8; i++) tot += ps[i];
        atomicAdd(&g_sumsq, (double)tot);
    }
}

// ============================================================
__global__ void k_final(float* __restrict__ out) {
    int t = threadIdx.x;                         // 1024 threads
    float p    = (float)g_counts[t] / (float)NTOK;
    float term = p * logf(p + 1e-10f);
    #pragma unroll
    for (int o = 16; o > 0; o >>= 1) term += __shfl_xor_sync(0xffffffffu, term, o);
    __shared__ float ws[32];
    if ((t & 31) == 0) ws[t >> 5] = term;
    __syncthreads();
    if (t < 32) {
        float v = ws[t];
        #pragma unroll
        for (int o = 16; o > 0; o >>= 1) v += __shfl_xor_sync(0xffffffffu, v, o);
        if (t == 0) {
            out[ND]     = (float)(1.25 * (g_sumsq / (double)ND));
            out[ND + 1] = expf(-v);
        }
    }
}

// ============================================================
extern "C" void kernel_launch(void* const* d_in, const int* in_sizes, int n_in,
                              void* d_out, int out_size) {
    const float* z = (const float*)d_in[0];      // [131072, 256]
    const float* w = (const float*)d_in[1];      // [1024, 256]
    float* out = (float*)d_out;

    cudaFuncSetAttribute(k_gemm, cudaFuncAttributeMaxDynamicSharedMemorySize, SMEM_TOTAL);

    k_init <<<1, 1024>>>();
    k_norm <<<NCODE, 64>>>(w);
    k_gemm <<<NTOK/128, 256, SMEM_TOTAL>>>(z);
    k_fin  <<<NTOK/8, 256>>>(z, w, out);
    k_final<<<1, 1024>>>(out);
}